// round 3
// baseline (speedup 1.0000x reference)
#include <cuda_runtime.h>
#include <cstdint>

#define NMAX 100000
#define EMAX 1600000

// ---------------- device scratch (no runtime allocation allowed) ----------
__device__ int   g_cnt[NMAX];
__device__ int   g_cur[NMAX];
__device__ int   g_off[NMAX + 1];
__device__ float g_dinv[NMAX];
__device__ int   g_srcs[EMAX];
__device__ alignas(16) float g_bufA[(size_t)NMAX * 128];  // activations
__device__ alignas(16) float g_bufG[(size_t)NMAX * 128];  // g = dinv*(X@W)

// ---------------- CSR build ------------------------------------------------
__global__ void k_zero(int n) {
    int i = blockIdx.x * blockDim.x + threadIdx.x;
    if (i < n) { g_cnt[i] = 0; g_cur[i] = 0; }
}

// edge_index is int32 (JAX x64 disabled): row 0 = src [0,E), row 1 = dst [E,2E)
__global__ void k_hist(const int* __restrict__ ei, int e, int n) {
    int i = blockIdx.x * blockDim.x + threadIdx.x;
    if (i < e) {
        int d = ei[e + i];
        if ((unsigned)d < (unsigned)n) atomicAdd(&g_cnt[d], 1);
    }
}

// single-block exclusive scan of g_cnt -> g_off, plus dinv = rsqrt(deg+1)
__global__ void k_scan(int n) {
    __shared__ int part[1024];
    int t  = threadIdx.x;
    int ch = (n + 1023) >> 10;
    int b  = t * ch;
    int en = min(n, b + ch);
    int s = 0;
    for (int i = b; i < en; i++) s += g_cnt[i];
    part[t] = s;
    __syncthreads();
    for (int off = 1; off < 1024; off <<= 1) {
        int v = (t >= off) ? part[t - off] : 0;
        __syncthreads();
        part[t] += v;
        __syncthreads();
    }
    int ex = (t == 0) ? 0 : part[t - 1];
    for (int i = b; i < en; i++) {
        g_off[i] = ex;
        int c = g_cnt[i];
        ex += c;
        g_dinv[i] = rsqrtf((float)(c + 1));  // +1 self loop
    }
    if (t == 1023) g_off[n] = part[1023];
}

__global__ void k_fill(const int* __restrict__ ei, int e, int n) {
    int i = blockIdx.x * blockDim.x + threadIdx.x;
    if (i < e) {
        int d = ei[e + i];
        int s = ei[i];
        if ((unsigned)d < (unsigned)n && (unsigned)s < (unsigned)n) {
            int pos = g_off[d] + atomicAdd(&g_cur[d], 1);
            g_srcs[pos] = s;
        }
    }
}

// ---------------- GEMM: g_bufG = dinv[row] * (X @ W) -----------------------
// X: [n,128] (external input if FROM_EXT, else g_bufA), W: [128,NCOL].
// 256 threads/block, 4x4 register tile.
template <int NCOL, bool FROM_EXT>
__global__ void k_gemm(const float* __restrict__ Xext, const float* __restrict__ W,
                       int n) {
    constexpr int TX  = NCOL / 4;     // threads across cols
    constexpr int TY  = 256 / TX;     // row groups
    constexpr int RPB = 4 * TY;       // rows per block
    constexpr int KC  = 64;           // k chunk

    __shared__ alignas(16) float Ws[KC * NCOL];
    __shared__ alignas(16) float Xs[RPB * 128];

    const float4* Xsrc = FROM_EXT ? (const float4*)Xext : (const float4*)g_bufA;

    int tid  = threadIdx.x;
    int row0 = blockIdx.x * RPB;

    // stage X tile (float4)
    for (int i = tid; i < RPB * 32; i += 256) {
        int r = i >> 5, c = i & 31;
        int gr = row0 + r;
        float4 v = (gr < n) ? Xsrc[(size_t)gr * 32 + c]
                            : make_float4(0.f, 0.f, 0.f, 0.f);
        ((float4*)Xs)[i] = v;
    }

    int tx = tid % TX, ty = tid / TX;
    int rbase = ty * 4;

    float acc[4][4];
#pragma unroll
    for (int r = 0; r < 4; r++)
#pragma unroll
        for (int c = 0; c < 4; c++) acc[r][c] = 0.f;

    for (int kc = 0; kc < 128; kc += KC) {
        __syncthreads();
        for (int i = tid; i < KC * NCOL / 4; i += 256)
            ((float4*)Ws)[i] = ((const float4*)W)[kc * (NCOL / 4) + i];
        __syncthreads();

#pragma unroll 4
        for (int k = 0; k < KC; k += 4) {
            float4 b0 = ((float4*)Ws)[(k + 0) * TX + tx];
            float4 b1 = ((float4*)Ws)[(k + 1) * TX + tx];
            float4 b2 = ((float4*)Ws)[(k + 2) * TX + tx];
            float4 b3 = ((float4*)Ws)[(k + 3) * TX + tx];
#pragma unroll
            for (int r = 0; r < 4; r++) {
                float4 a = ((float4*)Xs)[(rbase + r) * 32 + ((kc + k) >> 2)];
                acc[r][0] += a.x * b0.x; acc[r][1] += a.x * b0.y;
                acc[r][2] += a.x * b0.z; acc[r][3] += a.x * b0.w;
                acc[r][0] += a.y * b1.x; acc[r][1] += a.y * b1.y;
                acc[r][2] += a.y * b1.z; acc[r][3] += a.y * b1.w;
                acc[r][0] += a.z * b2.x; acc[r][1] += a.z * b2.y;
                acc[r][2] += a.z * b2.z; acc[r][3] += a.z * b2.w;
                acc[r][0] += a.w * b3.x; acc[r][1] += a.w * b3.y;
                acc[r][2] += a.w * b3.z; acc[r][3] += a.w * b3.w;
            }
        }
    }

#pragma unroll
    for (int r = 0; r < 4; r++) {
        int gr = row0 + rbase + r;
        if (gr < n) {
            float dv = g_dinv[gr];
            float4 o = make_float4(acc[r][0] * dv, acc[r][1] * dv,
                                   acc[r][2] * dv, acc[r][3] * dv);
            ((float4*)g_bufG)[(size_t)gr * (NCOL / 4) + tx] = o;
        }
    }
}

// ------- Aggregation: out[d] = act(dinv[d]*(G[d] + sum_{s} G[s]) + b) ------
// Reads g_bufG, writes g_bufA (128-col layers).
template <bool RELU>
__global__ void k_agg128(const float* __restrict__ bias, int n) {
    int w = (blockIdx.x * blockDim.x + threadIdx.x) >> 5;
    if (w >= n) return;
    int lane = threadIdx.x & 31;
    const float4* G = (const float4*)g_bufG;

    float4 acc = G[(size_t)w * 32 + lane];  // self loop
    int beg = g_off[w], end = g_off[w + 1];
    int i = beg;
    for (; i + 2 <= end; i += 2) {
        int s0 = g_srcs[i], s1 = g_srcs[i + 1];
        float4 v0 = G[(size_t)s0 * 32 + lane];
        float4 v1 = G[(size_t)s1 * 32 + lane];
        acc.x += v0.x + v1.x; acc.y += v0.y + v1.y;
        acc.z += v0.z + v1.z; acc.w += v0.w + v1.w;
    }
    if (i < end) {
        int s = g_srcs[i];
        float4 v = G[(size_t)s * 32 + lane];
        acc.x += v.x; acc.y += v.y; acc.z += v.z; acc.w += v.w;
    }
    float dv = g_dinv[w];
    float4 bb = ((const float4*)bias)[lane];
    float4 o = make_float4(acc.x * dv + bb.x, acc.y * dv + bb.y,
                           acc.z * dv + bb.z, acc.w * dv + bb.w);
    if (RELU) {
        o.x = fmaxf(o.x, 0.f); o.y = fmaxf(o.y, 0.f);
        o.z = fmaxf(o.z, 0.f); o.w = fmaxf(o.w, 0.f);
    }
    ((float4*)g_bufA)[(size_t)w * 32 + lane] = o;
}

// 64-col final layer: reads g_bufG, writes external output, no relu.
__global__ void k_agg64(const float* __restrict__ bias, float* __restrict__ O,
                        int n) {
    int w = (blockIdx.x * blockDim.x + threadIdx.x) >> 5;
    if (w >= n) return;
    int lane = threadIdx.x & 31;
    const float2* G = (const float2*)g_bufG;

    float2 acc = G[(size_t)w * 32 + lane];  // self loop
    int beg = g_off[w], end = g_off[w + 1];
    int i = beg;
    for (; i + 2 <= end; i += 2) {
        int s0 = g_srcs[i], s1 = g_srcs[i + 1];
        float2 v0 = G[(size_t)s0 * 32 + lane];
        float2 v1 = G[(size_t)s1 * 32 + lane];
        acc.x += v0.x + v1.x; acc.y += v0.y + v1.y;
    }
    if (i < end) {
        int s = g_srcs[i];
        float2 v = G[(size_t)s * 32 + lane];
        acc.x += v.x; acc.y += v.y;
    }
    float dv = g_dinv[w];
    float2 bb = ((const float2*)bias)[lane];
    float2 o = make_float2(acc.x * dv + bb.x, acc.y * dv + bb.y);
    ((float2*)O)[(size_t)w * 32 + lane] = o;
}

// ---------------- launch ----------------------------------------------------
extern "C" void kernel_launch(void* const* d_in, const int* in_sizes, int n_in,
                              void* d_out, int out_size) {
    const float* x  = (const float*)d_in[0];
    const int*   ei = (const int*)d_in[1];   // int32 edge_index [2, E]
    const float* W0 = (const float*)d_in[2];
    const float* b0 = (const float*)d_in[3];
    const float* W1 = (const float*)d_in[4];
    const float* b1 = (const float*)d_in[5];
    const float* W2 = (const float*)d_in[6];
    const float* b2 = (const float*)d_in[7];

    int n = in_sizes[0] / 128;   // 100000
    int e = in_sizes[1] / 2;     // 1600000

    // --- CSR build (once; reused by all 3 layers) ---
    k_zero<<<(n + 255) / 256, 256>>>(n);
    k_hist<<<(e + 255) / 256, 256>>>(ei, e, n);
    k_scan<<<1, 1024>>>(n);
    k_fill<<<(e + 255) / 256, 256>>>(ei, e, n);

    int aggGrid = (n + 7) / 8;  // 8 warps/block

    // --- layer 0 ---
    k_gemm<128, true ><<<(n + 31) / 32, 256>>>(x, W0, n);
    k_agg128<true><<<aggGrid, 256>>>(b0, n);
    // --- layer 1 ---
    k_gemm<128, false><<<(n + 31) / 32, 256>>>(nullptr, W1, n);
    k_agg128<true><<<aggGrid, 256>>>(b1, n);
    // --- layer 2 (64 cols, no relu, writes d_out) ---
    k_gemm<64, false><<<(n + 63) / 64, 256>>>(nullptr, W2, n);
    k_agg64<<<aggGrid, 256>>>(b2, (float*)d_out, n);
}